// round 14
// baseline (speedup 1.0000x reference)
#include <cuda_runtime.h>
#include <cuda_bf16.h>
#include <cstddef>
#include <cstdint>

// score(f) = 1 + tanh(f.W + b)/10 ; e[parent] = score(c0)*e[c0] + score(c1)*e[c1]
// Complete binary tree, level order, D=21, N = 2^21 - 1, F = 64.
// Phase A: warp-specialized pipeline per block: warp 7 = TMA producer
//          (cp.async.bulk 8KB tiles), warps 0-6 = consumers, each owning one
//          smem slot paced by full/empty mbarriers. Internal rows -> g_scores;
//          leaf rows -> level-19 parents directly. No block-wide syncs.
// Phase B: levels 19..12 as tiny score-lookup passes; 11..1 on block 0.

#define TANH_INV_SCALAR 0.1f
#define NB       444        // 3 blocks/SM on 148 SMs -> all resident
#define NT       256
#define NTH      (NB * NT)

#define NSLOTS      7
#define SLOT_BYTES  8192                  // 32 rows * 256 B
#define SLOT_F4     512                   // float4s per slot
#define SLOTS_TOTAL (NB * NSLOTS)         // 3108

#define LEAF_START  ((1 << 20) - 1)
#define N_INT_T32   (1 << 15)             // 32768 internal 32-row tiles
#define N_TILES32   (1 << 16)             // + 32768 leaf tiles

__device__ float g_scores[1 << 20];
__device__ unsigned g_count = 0;
__device__ volatile unsigned g_gen = 0;

__device__ __forceinline__ void grid_barrier()
{
    __syncthreads();
    if (threadIdx.x == 0) {
        __threadfence();
        unsigned g = g_gen;
        if (atomicAdd(&g_count, 1u) == NB - 1u) {
            g_count = 0;
            __threadfence();
            g_gen = g + 1u;
        } else {
            while (g_gen == g) { __nanosleep(32); }
            __threadfence();
        }
    }
    __syncthreads();
}

__device__ __forceinline__ float tanh_fast(float x)
{
    float y;
    asm("tanh.approx.f32 %0, %1;" : "=f"(y) : "f"(x));
    return y;
}

__device__ __forceinline__ int tile_base32(int T)
{
    return (T < N_INT_T32) ? (T << 5)
                           : LEAF_START + ((T - N_INT_T32) << 5);
}

__device__ __forceinline__ void mbar_init(unsigned a, unsigned cnt)
{
    asm volatile("mbarrier.init.shared.b64 [%0], %1;" :: "r"(a), "r"(cnt) : "memory");
}
__device__ __forceinline__ void mbar_wait(unsigned a, unsigned parity)
{
    asm volatile(
        "{\n\t.reg .pred P;\n\t"
        "W_%=:\n\t"
        "mbarrier.try_wait.parity.acquire.cta.shared::cta.b64 P, [%0], %1, 0x989680;\n\t"
        "@P bra.uni D_%=;\n\t"
        "bra.uni W_%=;\n\t"
        "D_%=:\n\t}"
        :: "r"(a), "r"(parity) : "memory");
}
__device__ __forceinline__ void mbar_arrive(unsigned a)
{
    asm volatile("mbarrier.arrive.shared.b64 _, [%0];" :: "r"(a) : "memory");
}
__device__ __forceinline__ void mbar_expect_tx(unsigned a, unsigned bytes)
{
    asm volatile("mbarrier.arrive.expect_tx.shared.b64 _, [%0], %1;"
                 :: "r"(a), "r"(bytes) : "memory");
}
__device__ __forceinline__ void bulk_copy(unsigned dst, const void* src,
                                          unsigned bytes, unsigned mbar)
{
    asm volatile(
        "cp.async.bulk.shared::cta.global.mbarrier::complete_tx::bytes "
        "[%0], [%1], %2, [%3];"
        :: "r"(dst), "l"(src), "r"(bytes), "r"(mbar) : "memory");
}

__global__ void __launch_bounds__(NT, 3)
tree_all_kernel(const float* __restrict__ features,
                const float* __restrict__ leaf_energy,
                const float* __restrict__ W,
                const float* __restrict__ bptr,
                float* __restrict__ energy)
{
    extern __shared__ float4 slots[];                 // NSLOTS * SLOT_F4
    __shared__ alignas(8) unsigned long long mbars[2 * NSLOTS]; // full[k], empty[k]

    const int tid  = threadIdx.x;
    const int lane = tid & 31;
    const int warp = tid >> 5;
    const int gtid = blockIdx.x * NT + tid;

    const unsigned full0  = (unsigned)__cvta_generic_to_shared(&mbars[0]);
    const unsigned empty0 = (unsigned)__cvta_generic_to_shared(&mbars[NSLOTS]);
    const unsigned slot0  = (unsigned)__cvta_generic_to_shared(&slots[0]);

    if (tid == 0) {
        for (int k = 0; k < NSLOTS; ++k) {
            mbar_init(full0  + 8u * k, 1u);
            mbar_init(empty0 + 8u * k, 1u);
        }
    }
    asm volatile("fence.proxy.async.shared::cta;" ::: "memory");
    __syncthreads();

    const float4 wv = reinterpret_cast<const float4*>(W)[lane & 15];
    const float  b  = __ldg(bptr);

    const bool s3 = lane & 8, s2 = lane & 4, s1 = lane & 2;
    const int  h  = lane >> 4;
    const int  vi = ((lane >> 3) & 1) | (((lane >> 2) & 1) << 1)
                  | (((lane >> 1) & 1) << 2);
    const int  rr = 2 * vi + h;

    // ================= Phase A =============================================
    if (warp == NSLOTS) {
        // -------- Producer (warp 7, lane 0 only) --------
        if (lane == 0) {
            unsigned epar = 0x7F;             // per-slot empty parity, start 1
            const int base = blockIdx.x * NSLOTS;
            for (int r = 0; r * SLOTS_TOTAL + base < N_TILES32; ++r) {
                #pragma unroll
                for (int k = 0; k < NSLOTS; ++k) {
                    const int T = r * SLOTS_TOTAL + base + k;
                    if (T < N_TILES32) {
                        mbar_wait(empty0 + 8u * k, (epar >> k) & 1u);
                        epar ^= (1u << k);
                        mbar_expect_tx(full0 + 8u * k, SLOT_BYTES);
                        bulk_copy(slot0 + (unsigned)k * SLOT_BYTES,
                                  features + (size_t)tile_base32(T) * 64,
                                  SLOT_BYTES, full0 + 8u * k);
                    }
                }
            }
        }
    } else {
        // -------- Consumer (warps 0..6, slot = warp) --------
        const int k = warp;
        const float4* slot = slots + k * SLOT_F4;
        unsigned fpar = 0;
        for (int T = blockIdx.x * NSLOTS + k; T < N_TILES32; T += SLOTS_TOTAL) {
            const int  cb      = tile_base32(T);
            const bool is_leaf = (T >= N_INT_T32);
            const int  t       = T - N_INT_T32;     // leaf-relative tile

            mbar_wait(full0 + 8u * k, fpar);
            fpar ^= 1u;

            #pragma unroll
            for (int g = 0; g < 2; ++g) {
                // leaf-energy prefetch (independent of the dot)
                float e = 0.0f;
                if (is_leaf)
                    e = __ldg(&leaf_energy[(t << 5) + (g << 4) + rr]);

                float part[8];
                #pragma unroll
                for (int j = 0; j < 8; ++j) {
                    float4 f = slot[g * 256 + j * 32 + lane];
                    part[j] = f.x * wv.x + f.y * wv.y + f.z * wv.z + f.w * wv.w;
                }
                float a4[4];
                #pragma unroll
                for (int j = 0; j < 4; ++j) {
                    float u0 = part[2*j]   + __shfl_xor_sync(~0u, part[2*j],   8);
                    float u1 = part[2*j+1] + __shfl_xor_sync(~0u, part[2*j+1], 8);
                    a4[j] = s3 ? u1 : u0;
                }
                float a2[2];
                #pragma unroll
                for (int j = 0; j < 2; ++j) {
                    float u0 = a4[2*j]   + __shfl_xor_sync(~0u, a4[2*j],   4);
                    float u1 = a4[2*j+1] + __shfl_xor_sync(~0u, a4[2*j+1], 4);
                    a2[j] = s2 ? u1 : u0;
                }
                float u0 = a2[0] + __shfl_xor_sync(~0u, a2[0], 2);
                float u1 = a2[1] + __shfl_xor_sync(~0u, a2[1], 2);
                float a1 = s1 ? u1 : u0;
                float dot = a1 + __shfl_xor_sync(~0u, a1, 1);

                float sc = 1.0f + tanh_fast(dot + b) * TANH_INV_SCALAR;
                const int node = cb + (g << 4) + rr;

                if (!is_leaf) {
                    if ((lane & 1) == 0 && node < LEAF_START)
                        __stcg(&g_scores[node], sc);
                } else {
                    if ((lane & 1) == 0)
                        __stcg(&energy[node], e);         // seed output leaves
                    float contrib = sc * e;
                    float other = __shfl_xor_sync(~0u, contrib, 16);
                    if (h == 0 && (lane & 1) == 0)
                        __stcg(&energy[(1 << 19) - 1 + (t << 4) + (g << 3) + vi],
                               contrib + other);          // level-19 parents
                }
            }
            __syncwarp();
            if (lane == 0) mbar_arrive(empty0 + 8u * k);
        }
    }
    grid_barrier();

    // ================= Phase B: levels d = 19 .. 12 (score lookups) =========
    for (int d = 19; d >= 12; --d) {
        const int np     = 1 << (d - 1);
        const int pstart = np - 1;
        for (int i = gtid; i < np; i += NTH) {
            const int p = pstart + i;
            const int c = 2 * p + 1;
            float sc0 = __ldcg(&g_scores[c]);
            float sc1 = __ldcg(&g_scores[c + 1]);
            float e0 = __ldcg(&energy[c]);
            float e1 = __ldcg(&energy[c + 1]);
            __stcg(&energy[p], sc0 * e0 + sc1 * e1);
        }
        grid_barrier();
    }

    // ================= Tail: levels d = 11 .. 1 on block 0 ==================
    if (blockIdx.x != 0) return;
    for (int d = 11; d >= 1; --d) {
        const int np     = 1 << (d - 1);
        const int pstart = np - 1;
        for (int i = tid; i < np; i += NT) {
            const int p = pstart + i;
            const int c = 2 * p + 1;
            float sc0 = __ldcg(&g_scores[c]);
            float sc1 = __ldcg(&g_scores[c + 1]);
            float e0 = __ldcg(&energy[c]);
            float e1 = __ldcg(&energy[c + 1]);
            __stcg(&energy[p], sc0 * e0 + sc1 * e1);
        }
        __syncthreads();
    }
}

extern "C" void kernel_launch(void* const* d_in, const int* in_sizes, int n_in,
                              void* d_out, int out_size)
{
    const float* features    = (const float*)d_in[0];   // [N, 64]
    const float* leaf_energy = (const float*)d_in[1];   // [2^20]
    const float* W           = (const float*)d_in[2];   // [64]
    const float* bptr        = (const float*)d_in[3];   // [1]
    float* energy = (float*)d_out;                      // [N]

    const int smem = NSLOTS * SLOT_BYTES;               // 57,344 B dynamic
    cudaFuncSetAttribute(tree_all_kernel,
                         cudaFuncAttributeMaxDynamicSharedMemorySize, smem);
    tree_all_kernel<<<NB, NT, smem>>>(features, leaf_energy, W, bptr, energy);
}

// round 17
// speedup vs baseline: 1.2416x; 1.2416x over previous
#include <cuda_runtime.h>
#include <cuda_bf16.h>
#include <cstddef>

// score(f) = 1 + tanh(f.W + b)/10 ; e[parent] = score(c0)*e[c0] + score(c1)*e[c1]
// Complete binary tree, level order, D=21, N = 2^21 - 1, F = 64.
// Phase A (R11): flat barrier-free pass over all rows, 1-buffer register
//   pipeline, __ldcs evict-first feature reads. Internal rows -> g_scores;
//   leaf rows -> level-19 parents directly.
// Phase B: ONE grid barrier, then each warp reduces a level-12 subtree,
//   WRITING EVERY intermediate level (18..12) to energy[] as it folds.
// Tail: levels d = 12 .. 1 on block 0 (children start at level 12).

#define TANH_INV_SCALAR 0.1f
#define NB       444        // 3 blocks/SM on 148 SMs -> all resident
#define NT       256
#define WPB      (NT / 32)
#define NWARPS   (NB * WPB)

#define LEAF_START ((1 << 20) - 1)
#define N_INT_TILES (1 << 16)     // tiles covering rows 0 .. 2^20-1
#define N_TILES     (1 << 17)     // + 65536 leaf tiles

__device__ float g_scores[1 << 20];     // scores for internal nodes (by node id)
__device__ unsigned g_count = 0;
__device__ volatile unsigned g_gen = 0;

__device__ __forceinline__ void grid_barrier()
{
    __syncthreads();
    if (threadIdx.x == 0) {
        __threadfence();
        unsigned g = g_gen;
        if (atomicAdd(&g_count, 1u) == NB - 1u) {
            g_count = 0;
            __threadfence();
            g_gen = g + 1u;
        } else {
            while (g_gen == g) { __nanosleep(32); }
            __threadfence();
        }
    }
    __syncthreads();
}

__device__ __forceinline__ float tanh_fast(float x)
{
    float y;
    asm("tanh.approx.f32 %0, %1;" : "=f"(y) : "f"(x));
    return y;
}

__device__ __forceinline__ int tile_base(int T)
{
    return (T < N_INT_TILES) ? (T << 4)
                             : LEAF_START + ((T - N_INT_TILES) << 4);
}

// Evict-first streaming loads: features are touched exactly once.
__device__ __forceinline__ void issue_loads(const float* __restrict__ features,
                                            int cb, int lane, float4 v[8])
{
    const float4* g = reinterpret_cast<const float4*>(features + (size_t)cb * 64);
    #pragma unroll
    for (int j = 0; j < 8; ++j)
        v[j] = __ldcs(&g[j * 32 + lane]);
}

__global__ void __launch_bounds__(NT, 3)
tree_all_kernel(const float* __restrict__ features,
                const float* __restrict__ leaf_energy,
                const float* __restrict__ W,
                const float* __restrict__ bptr,
                float* __restrict__ energy)
{
    __shared__ float subbuf[WPB][64];      // per-warp subtree scratch

    const int tid   = threadIdx.x;
    const int lane  = tid & 31;
    const int warp  = tid >> 5;
    const int gtid  = blockIdx.x * NT + tid;
    const int gwarp = gtid >> 5;

    const float4 wv = reinterpret_cast<const float4*>(W)[lane & 15];
    const float  b  = __ldg(bptr);

    const bool s3 = lane & 8, s2 = lane & 4, s1 = lane & 2;
    const int  h  = lane >> 4;
    const int  vi = ((lane >> 3) & 1) | (((lane >> 2) & 1) << 1)
                  | (((lane >> 1) & 1) << 2);
    const int  rr = 2 * vi + h;

    // ================= Phase A: flat scoring pass (R11) =====================
    {
        int T = gwarp;
        float4 v[8];
        if (T < N_TILES)
            issue_loads(features, tile_base(T), lane, v);

        while (T < N_TILES) {
            const int  cb      = tile_base(T);
            const bool is_leaf = (T >= N_INT_TILES);
            const int  Tn      = T + NWARPS;

            float part[8];
            #pragma unroll
            for (int j = 0; j < 8; ++j)
                part[j] = v[j].x * wv.x + v[j].y * wv.y
                        + v[j].z * wv.z + v[j].w * wv.w;

            float e = 0.0f;
            if (is_leaf)
                e = __ldg(&leaf_energy[cb + rr - LEAF_START]);

            if (Tn < N_TILES)
                issue_loads(features, tile_base(Tn), lane, v);

            float a4[4];
            #pragma unroll
            for (int j = 0; j < 4; ++j) {
                float u0 = part[2*j]   + __shfl_xor_sync(~0u, part[2*j],   8);
                float u1 = part[2*j+1] + __shfl_xor_sync(~0u, part[2*j+1], 8);
                a4[j] = s3 ? u1 : u0;
            }
            float a2[2];
            #pragma unroll
            for (int j = 0; j < 2; ++j) {
                float u0 = a4[2*j]   + __shfl_xor_sync(~0u, a4[2*j],   4);
                float u1 = a4[2*j+1] + __shfl_xor_sync(~0u, a4[2*j+1], 4);
                a2[j] = s2 ? u1 : u0;
            }
            float u0 = a2[0] + __shfl_xor_sync(~0u, a2[0], 2);
            float u1 = a2[1] + __shfl_xor_sync(~0u, a2[1], 2);
            float a1 = s1 ? u1 : u0;
            float dot = a1 + __shfl_xor_sync(~0u, a1, 1);

            float sc = 1.0f + tanh_fast(dot + b) * TANH_INV_SCALAR;

            if (!is_leaf) {
                if ((lane & 1) == 0 && cb + rr < LEAF_START)
                    __stcg(&g_scores[cb + rr], sc);
            } else {
                if ((lane & 1) == 0)
                    __stcg(&energy[cb + rr], e);          // seed output leaves
                float contrib = sc * e;
                float other = __shfl_xor_sync(~0u, contrib, 16);
                if (h == 0 && (lane & 1) == 0) {
                    const int t = T - N_INT_TILES;
                    __stcg(&energy[(1 << 19) - 1 + 8 * t + vi],
                           contrib + other);              // level-19 parents
                }
            }
            T = Tn;
        }
    }
    grid_barrier();          // the ONLY grid-wide sync between phases

    // ====== Phase B: per-warp level-12 subtree reduction ====================
    // Each warp reduces one subtree rooted at level-12 node p, writing EVERY
    // level (18..12) to energy[]. Level-k descendants of p occupy
    // [((p+1)<<k)-1, ((p+2)<<k)-1).
    {
        float* buf = subbuf[warp];
        const int NROOT = 1 << 12;
        for (int root = gwarp; root < NROOT; root += NWARPS) {
            const int p  = NROOT - 1 + root;      // level-12 node
            const int b7 = ((p + 1) << 7) - 1;    // level-19 descendants
            const int b6 = ((p + 1) << 6) - 1;    // level-18 descendants

            // Level 19 -> 18: 128 contribs, pair-sum via xor-1.
            #pragma unroll
            for (int j = 0; j < 4; ++j) {
                const int i = lane + 32 * j;
                float e = __ldcg(&energy[b7 + i]);
                float s = __ldcg(&g_scores[b7 + i]);
                float c = s * e;
                float o = __shfl_xor_sync(~0u, c, 1);
                if ((lane & 1) == 0) {
                    const int m = i >> 1;
                    buf[m] = c + o;
                    __stcg(&energy[b6 + m], c + o);       // level-18 output
                }
            }
            __syncwarp();

            // Levels 18 (k=6) .. 13 (k=1): combine 2^k -> 2^(k-1).
            #pragma unroll
            for (int k = 6; k >= 1; --k) {
                const int half = 1 << (k - 1);
                const int bk   = ((p + 1) << k) - 1;       // children base
                const int bp   = ((p + 1) << (k - 1)) - 1; // parents base
                float nv = 0.0f;
                if (lane < half) {
                    float v0 = buf[2 * lane];
                    float v1 = buf[2 * lane + 1];
                    float sc0 = __ldcg(&g_scores[bk + 2 * lane]);
                    float sc1 = __ldcg(&g_scores[bk + 2 * lane + 1]);
                    nv = sc0 * v0 + sc1 * v1;
                }
                __syncwarp();
                if (lane < half) {
                    buf[lane] = nv;
                    __stcg(&energy[bp + lane], nv);        // level 17..12 output
                }
                __syncwarp();
            }
        }
    }
    grid_barrier();

    // ====== Tail: levels d = 12 .. 1 on block 0 (children start @ level 12) =
    if (blockIdx.x != 0) return;
    for (int d = 12; d >= 1; --d) {
        const int np     = 1 << (d - 1);
        const int pstart = np - 1;
        for (int i = tid; i < np; i += NT) {
            const int p = pstart + i;
            const int c = 2 * p + 1;
            float sc0 = __ldcg(&g_scores[c]);
            float sc1 = __ldcg(&g_scores[c + 1]);
            float e0 = __ldcg(&energy[c]);
            float e1 = __ldcg(&energy[c + 1]);
            __stcg(&energy[p], sc0 * e0 + sc1 * e1);
        }
        __syncthreads();
    }
}

extern "C" void kernel_launch(void* const* d_in, const int* in_sizes, int n_in,
                              void* d_out, int out_size)
{
    const float* features    = (const float*)d_in[0];   // [N, 64]
    const float* leaf_energy = (const float*)d_in[1];   // [2^20]
    const float* W           = (const float*)d_in[2];   // [64]
    const float* bptr        = (const float*)d_in[3];   // [1]
    float* energy = (float*)d_out;                      // [N]

    tree_all_kernel<<<NB, NT>>>(features, leaf_energy, W, bptr, energy);
}